// round 4
// baseline (speedup 1.0000x reference)
#include <cuda_runtime.h>
#include <cstdint>

#define NB   32
#define SEQL 256
#define NH   128
#define NVOC 10
#define NDIG 128
#define NT   129
#define TP   144    // [0,4) zero halo, [4,133) data (t=0..128), [133,144) zero halo
#define HALO 4
#define NITER 131
#define NG   4      // CTAs (channel groups) per batch
#define OC   32     // output channels per CTA
#define NTHREADS 512
#define PCH  18     // padded per-thread partial chunk (u64), 16B aligned, bank-spread

typedef unsigned long long u64t;

// Double-buffered hidden state (L2-resident), halos stay zero.
__device__ float g_h[2][NB][NH][TP];

// ---------- packed f32x2 helpers ----------
__device__ __forceinline__ u64t pk2(float a, float b){
    u64t r; asm("mov.b64 %0, {%1, %2};" : "=l"(r) : "f"(a), "f"(b)); return r;
}
__device__ __forceinline__ void fma2(u64t& d, u64t a, u64t b){
    asm("fma.rn.f32x2 %0, %1, %2, %0;" : "+l"(d) : "l"(a), "l"(b));
}
__device__ __forceinline__ u64t add2(u64t a, u64t b){
    u64t r; asm("add.rn.f32x2 %0, %1, %2;" : "=l"(r) : "l"(a), "l"(b)); return r;
}
__device__ __forceinline__ void unpk2(u64t v, float& a, float& b){
    asm("mov.b64 {%0, %1}, %2;" : "=f"(a), "=f"(b) : "l"(v));
}
__device__ __forceinline__ float lo2(u64t v){ float a,b; unpk2(v,a,b); return a; }
__device__ __forceinline__ float hi2(u64t v){ float a,b; unpk2(v,a,b); return b; }
__device__ __forceinline__ void cp16(uint32_t d, const void* s){
    asm volatile("cp.async.cg.shared.global [%0], [%1], 16;" :: "r"(d), "l"(s));
}

#define CLUSTER_SYNC() do { \
    asm volatile("barrier.cluster.arrive.aligned;" ::: "memory"); \
    asm volatile("barrier.cluster.wait.aligned;"   ::: "memory"); } while(0)

// Thread decode: og=tid[0:3) (4 out-ch), ttlo=tid[3:5), cg=tid[5:7) (32-ch quarter), A=tid[7:9).
// tt = A*4+ttlo (16 t-tiles of 8), t0 = tt*8. lt = index within cg group (0..127).
template<int D>
__device__ __forceinline__ void conv_iter(
    const float* __restrict__ src, float* __restrict__ dst,
    float* __restrict__ hs, uint32_t hs_sh,
    const float* __restrict__ ws, const float* __restrict__ cb,
    u64t* __restrict__ pbuf, float* __restrict__ pbuf2, int obase)
{
    const int tid  = threadIdx.x;
    const int og   = tid & 7;
    const int ttlo = (tid >> 3) & 3;
    const int cg   = (tid >> 5) & 3;
    const int A    = tid >> 7;
    const int lt   = (tid & 31) | (A << 5);
    const int tt   = A*4 + ttlo;
    const int t0   = tt * 8;
    const int cbase = cg * 32;

    // ---- stage own 32-channel quarter (18 KB) from L2 via cp.async ----
    {
        const float4* sp = (const float4*)(src + cbase*TP) + lt;
        uint32_t dp = hs_sh + (uint32_t)(cbase*TP + lt*4) * 4u;
        #pragma unroll
        for (int i = 0; i < 9; i++)
            cp16(dp + i*2048u, sp + i*128);
        asm volatile("cp.async.commit_group;\n\tcp.async.wait_group 0;" ::: "memory");
    }
    asm volatile("bar.sync %0, 128;" :: "r"(1 + cg) : "memory");

    const bool sp128 = (tt == 15);   // these threads also produce t=128

    u64t acc[4][4];
    #pragma unroll
    for (int oi = 0; oi < 4; oi++)
        #pragma unroll
        for (int p = 0; p < 4; p++) acc[oi][p] = 0ull;
    float accx[4] = {0.f, 0.f, 0.f, 0.f};

    // s-window: 16 floats at cols [t0, t0+16) = t in [t0-4, t0+12). u[j] = pair at col t0+2j.
    const char*   hb = (const char*)(hs + cbase*TP + t0);
    const float4* wq = (const float4*)ws + cbase*24 + og;   // ws[(c*3+k)*32 + o]

    #pragma unroll 2
    for (int c = 0; c < 32; c++){
        ulonglong2 a0 = *(const ulonglong2*)(hb);
        ulonglong2 a1 = *(const ulonglong2*)(hb + 16);
        ulonglong2 a2 = *(const ulonglong2*)(hb + 32);
        ulonglong2 a3 = *(const ulonglong2*)(hb + 48);
        float4 w0 = wq[0], w1 = wq[8], w2 = wq[16];
        u64t u[8] = {a0.x, a0.y, a1.x, a1.y, a2.x, a2.y, a3.x, a3.y};

        if (D != 1){
            // tap operand u-shift: pair p, offset d -> u[p + 2 + d/2]
            constexpr int S0 = (D == 4) ? 0 : 1;
            constexpr int S2 = (D == 4) ? 4 : 3;
            #define DOO(oi, v0, v1, v2) do {                                   \
                u64t d0 = pk2((v0),(v0)), d1 = pk2((v1),(v1)), d2 = pk2((v2),(v2)); \
                fma2(acc[oi][0], d0, u[S0+0]); fma2(acc[oi][1], d0, u[S0+1]);  \
                fma2(acc[oi][2], d0, u[S0+2]); fma2(acc[oi][3], d0, u[S0+3]);  \
                fma2(acc[oi][0], d1, u[2]);    fma2(acc[oi][1], d1, u[3]);     \
                fma2(acc[oi][2], d1, u[4]);    fma2(acc[oi][3], d1, u[5]);     \
                fma2(acc[oi][0], d2, u[S2+0]); fma2(acc[oi][1], d2, u[S2+1]);  \
                fma2(acc[oi][2], d2, u[S2+2]); fma2(acc[oi][3], d2, u[S2+3]);  \
            } while(0)
            DOO(0, w0.x, w1.x, w2.x);
            DOO(1, w0.y, w1.y, w2.y);
            DOO(2, w0.z, w1.z, w2.z);
            DOO(3, w0.w, w1.w, w2.w);
            #undef DOO
        } else {
            float s[16];
            #pragma unroll
            for (int j = 0; j < 8; j++) unpk2(u[j], s[2*j], s[2*j+1]);
            u64t om[6];
            #pragma unroll
            for (int j = 1; j < 6; j++) om[j] = pk2(s[2*j+1], s[2*j+2]);
            // d=-1 -> om[p+1]; d=0 -> u[p+2]; d=+1 -> om[p+2]
            #define DOO1(oi, v0, v1, v2) do {                                  \
                u64t d0 = pk2((v0),(v0)), d1 = pk2((v1),(v1)), d2 = pk2((v2),(v2)); \
                fma2(acc[oi][0], d0, om[1]); fma2(acc[oi][1], d0, om[2]);      \
                fma2(acc[oi][2], d0, om[3]); fma2(acc[oi][3], d0, om[4]);      \
                fma2(acc[oi][0], d1, u[2]);  fma2(acc[oi][1], d1, u[3]);       \
                fma2(acc[oi][2], d1, u[4]);  fma2(acc[oi][3], d1, u[5]);       \
                fma2(acc[oi][0], d2, om[2]); fma2(acc[oi][1], d2, om[3]);      \
                fma2(acc[oi][2], d2, om[4]); fma2(acc[oi][3], d2, om[5]);      \
            } while(0)
            DOO1(0, w0.x, w1.x, w2.x);
            DOO1(1, w0.y, w1.y, w2.y);
            DOO1(2, w0.z, w1.z, w2.z);
            DOO1(3, w0.w, w1.w, w2.w);
            #undef DOO1
        }

        if (sp128){
            // t=128 taps: t-D -> col 132-D, t -> col 132, t+D -> halo zero
            const float tm = (D == 4) ? lo2(u[4]) : (D == 2 ? lo2(u[5]) : hi2(u[5]));
            const float tz = lo2(u[6]);
            accx[0] = fmaf(w0.x, tm, fmaf(w1.x, tz, accx[0]));
            accx[1] = fmaf(w0.y, tm, fmaf(w1.y, tz, accx[1]));
            accx[2] = fmaf(w0.z, tm, fmaf(w1.z, tz, accx[2]));
            accx[3] = fmaf(w0.w, tm, fmaf(w1.w, tz, accx[3]));
        }

        hb += TP*4;
        wq += 24;
    }

    // ---- cg>0: store partials (8 aligned STS.128 per thread) ----
    if (cg != 0){
        u64t* pb = pbuf + (cg - 1)*(128*PCH) + lt*PCH;
        #pragma unroll
        for (int oi = 0; oi < 4; oi++){
            *(ulonglong2*)(pb + oi*4)     = make_ulonglong2(acc[oi][0], acc[oi][1]);
            *(ulonglong2*)(pb + oi*4 + 2) = make_ulonglong2(acc[oi][2], acc[oi][3]);
        }
    }
    if (sp128){
        #pragma unroll
        for (int oi = 0; oi < 4; oi++)
            pbuf2[cg*32 + og*4 + oi] = accx[oi];
    }
    __syncthreads();

    // ---- cg==0: reduce in registers, bias+relu+residual, write to dst ----
    if (cg == 0){
        #pragma unroll
        for (int q = 0; q < 3; q++){
            const u64t* pb = pbuf + q*(128*PCH) + lt*PCH;
            #pragma unroll
            for (int oi = 0; oi < 4; oi++){
                ulonglong2 v0 = *(const ulonglong2*)(pb + oi*4);
                ulonglong2 v1 = *(const ulonglong2*)(pb + oi*4 + 2);
                acc[oi][0] = add2(acc[oi][0], v0.x);
                acc[oi][1] = add2(acc[oi][1], v0.y);
                acc[oi][2] = add2(acc[oi][2], v1.x);
                acc[oi][3] = add2(acc[oi][3], v1.y);
            }
        }
        #pragma unroll
        for (int oi = 0; oi < 4; oi++){
            const int   o    = og*4 + oi;
            const float bias = cb[o];
            const float* hres = hs  + (obase + o)*TP + HALO + t0;
            float*       drow = dst + (obase + o)*TP + HALO + t0;
            #pragma unroll
            for (int p = 0; p < 4; p++){
                float r0, r1; unpk2(acc[oi][p], r0, r1);
                float2 h2 = *(const float2*)(hres + 2*p);
                float2 v;
                v.x = fmaxf(r0 + bias, 0.f) + h2.x;
                v.y = fmaxf(r1 + bias, 0.f) + h2.y;
                __stcg((float2*)(drow + 2*p), v);
            }
        }
    }
    // t = 128 finalize
    if (tid < 32){
        float s = pbuf2[tid] + pbuf2[32 + tid] + pbuf2[64 + tid] + pbuf2[96 + tid];
        float v = fmaxf(s + cb[tid], 0.f) + hs[(obase + tid)*TP + HALO + 128];
        __stcg(dst + (obase + tid)*TP + HALO + 128, v);
    }
}

__global__ void __cluster_dims__(NG, 1, 1) __launch_bounds__(NTHREADS, 1)
vgt_kernel(const int* __restrict__ x, const float* __restrict__ emb_w,
           const float* __restrict__ red_w, const float* __restrict__ red_b,
           const float* __restrict__ conv_w, const float* __restrict__ conv_b,
           const float* __restrict__ out_w, const float* __restrict__ out_b,
           float* __restrict__ out)
{
    extern __shared__ __align__(16) unsigned char smraw[];
    u64t*  pbuf  = (u64t*)smraw;                    // 3*128*18 u64 = 54 KB
    float* hs    = (float*)(pbuf + 3*128*PCH);      // NH*TP = 18432 floats
    float* ws    = hs + NH*TP;                      // 12288
    float* cb    = ws + NH*3*OC;                    // 32
    float* m1    = cb + OC;                         // 320
    float* m2    = m1 + NVOC*OC;                    // 320
    float* pbuf2 = m2 + NVOC*OC;                    // 128

    const uint32_t hs_sh = (uint32_t)__cvta_generic_to_shared(hs);

    const int tid   = threadIdx.x;
    const int b     = blockIdx.x >> 2;
    const int g     = blockIdx.x & 3;
    const int obase = g * OC;

    // ---- prologue: weights, reducer tables, zero state ----
    for (int idx = tid; idx < NH*3*OC; idx += NTHREADS){
        int ol = idx & 31;
        int ck = idx >> 5;          // = c*3 + k
        int k  = ck % 3;
        int c  = ck / 3;
        ws[idx] = conv_w[((obase + ol)*NH + c)*3 + k];
    }
    if (tid < OC) cb[tid] = conv_b[obase + tid];

    for (int idx = tid; idx < NVOC*OC; idx += NTHREADS){
        int v  = idx / OC;
        int ol = idx % OC;
        const float* rw = red_w + (obase + ol)*(2*NH);
        const float* ew = emb_w + v*NH;
        float s1 = 0.f, s2 = 0.f;
        for (int c = 0; c < NH; c++){
            float e = ew[c];
            s1 = fmaf(rw[c],      e, s1);
            s2 = fmaf(rw[NH + c], e, s2);
        }
        m1[idx] = s1;
        m2[idx] = s2;
    }

    for (int idx = tid; idx < 2*OC*TP; idx += NTHREADS){
        int bb = idx / (OC*TP);
        int r  = idx - bb*(OC*TP);
        int c  = r / TP;
        int t  = r - c*TP;
        __stcg(&g_h[bb][b][obase + c][t], 0.f);
    }
    __syncthreads();

    // h0 = relu(M1[x[t]] + M2[x[t+128]] + red_b)
    {
        const int*   xb  = x + b*SEQL;
        const float* rbp = red_b + obase;
        for (int idx = tid; idx < OC*NDIG; idx += NTHREADS){
            int ol = idx >> 7;
            int t  = idx & 127;
            int v1 = xb[t];
            int v2 = xb[t + NDIG];
            float val = m1[v1*OC + ol] + m2[v2*OC + ol] + rbp[ol];
            __stcg(&g_h[0][b][obase + ol][HALO + t], fmaxf(val, 0.f));
        }
    }
    CLUSTER_SYNC();

    // ---- 131 residual conv iterations ----
    int cur = 0;
    #pragma unroll 1
    for (int i = 0; i < 4; i++){
        conv_iter<1>(&g_h[cur][b][0][0], &g_h[cur^1][b][0][0], hs, hs_sh, ws, cb, pbuf, pbuf2, obase);
        CLUSTER_SYNC();
        cur ^= 1;
    }
    #pragma unroll 1
    for (int i = 0; i < 4; i++){
        conv_iter<2>(&g_h[cur][b][0][0], &g_h[cur^1][b][0][0], hs, hs_sh, ws, cb, pbuf, pbuf2, obase);
        CLUSTER_SYNC();
        cur ^= 1;
    }
    #pragma unroll 1
    for (int i = 0; i < NITER - 8; i++){
        conv_iter<4>(&g_h[cur][b][0][0], &g_h[cur^1][b][0][0], hs, hs_sh, ws, cb, pbuf, pbuf2, obase);
        CLUSTER_SYNC();
        cur ^= 1;
    }

    // ---- output head ----
    {
        const float4* s4 = (const float4*)&g_h[cur][b][0][0];
        float4*       d4 = (float4*)hs;
        #pragma unroll
        for (int i = 0; i < (NH*TP/4)/NTHREADS; i++)
            d4[tid + i*NTHREADS] = __ldcg(s4 + tid + i*NTHREADS);
    }
    __syncthreads();

    const int tstart = g * 33;
    const int tcnt   = (NT - tstart) < 33 ? (NT - tstart) : 33;
    for (int idx = tid; idx < tcnt*NVOC; idx += NTHREADS){
        int t = tstart + idx / NVOC;
        int o = idx % NVOC;
        const float* wrow = out_w + o*NH;
        float s = out_b[o];
        #pragma unroll 8
        for (int c = 0; c < NH; c++)
            s = fmaf(wrow[c], hs[c*TP + HALO + t], s);
        out[(b*NT + t)*NVOC + o] = s;
    }
}

extern "C" void kernel_launch(void* const* d_in, const int* in_sizes, int n_in,
                              void* d_out, int out_size)
{
    (void)in_sizes; (void)n_in; (void)out_size;
    const int*   x      = (const int*)  d_in[0];
    const float* emb_w  = (const float*)d_in[1];
    const float* red_w  = (const float*)d_in[2];
    const float* red_b  = (const float*)d_in[3];
    const float* conv_w = (const float*)d_in[4];
    const float* conv_b = (const float*)d_in[5];
    const float* out_w  = (const float*)d_in[6];
    const float* out_b  = (const float*)d_in[7];
    float* out = (float*)d_out;

    const size_t smem = (size_t)(3*128*PCH)*sizeof(u64t) +
        (size_t)(NH*TP + NH*3*OC + OC + 2*NVOC*OC + 128) * sizeof(float); // ~178 KB
    cudaFuncSetAttribute(vgt_kernel, cudaFuncAttributeMaxDynamicSharedMemorySize, (int)smem);
    vgt_kernel<<<NB*NG, NTHREADS, smem>>>(x, emb_w, red_w, red_b,
                                          conv_w, conv_b, out_w, out_b, out);
}